// round 2
// baseline (speedup 1.0000x reference)
#include <cuda_runtime.h>
#include <cstdint>

#define D_LEN 32768

// ---------------- scratch (static device globals, no allocation) ------------
__device__ __align__(256) float g_a[64 * D_LEN];
__device__ __align__(256) float g_s[64 * D_LEN];
__device__ __align__(256) float g_c[64 * D_LEN];
__device__ double g_part[640];

__constant__ int c_PI[10] = {0,0,0,0,1,1,1,2,2,3};
__constant__ int c_PJ[10] = {0,1,2,3,1,2,3,2,3,3};

// ---------------- pool(4) + accurate sincos(100*m) --------------------------
__global__ void pool_kernel(const float* __restrict__ A, const float* __restrict__ B) {
    int idx = blockIdx.x * blockDim.x + threadIdx.x;   // [0, 2*32*32768)
    int tensor = idx >> 20;
    int rem = idx & 1048575;
    int b    = rem >> 15;                              // 0..31
    int feat = rem & 32767;                            // c*256 + ph*16 + pw
    int c  = feat >> 8;
    int ph = (feat >> 4) & 15;
    int pw = feat & 15;
    const float* src = tensor ? B : A;
    const float* p = src + ((((b * 128 + c) * 64) + ph * 4) * 64 + pw * 4);
    float4 r0 = *(const float4*)(p);
    float4 r1 = *(const float4*)(p + 64);
    float4 r2 = *(const float4*)(p + 128);
    float4 r3 = *(const float4*)(p + 192);
    float sum = ((r0.x + r0.y) + (r0.z + r0.w))
              + ((r1.x + r1.y) + (r1.z + r1.w))
              + ((r2.x + r2.y) + (r2.z + r2.w))
              + ((r3.x + r3.y) + (r3.z + r3.w));
    float m = sum * 0.0625f;

    // sincos(100*m): double range reduction, float polys on [-pi/4, pi/4]
    double xd = 100.0 * (double)m;
    double kd = rint(xd * 0.63661977236758134308);     // 2/pi
    int q = (int)kd;
    float r = (float)(xd - kd * 1.5707963267948966);
    float z = r * r;
    float ps = fmaf(z, fmaf(z, -1.9515295891e-4f, 8.3321608736e-3f), -1.6666654611e-1f);
    float sinr = fmaf(r * z, ps, r);
    float pc = fmaf(z, fmaf(z, 2.443315711809948e-5f, -1.388731625493765e-3f),
                    4.166664568298827e-2f);
    float cosr = fmaf(z * z, pc, fmaf(z, -0.5f, 1.0f));
    float s, cc;
    if (q & 1) { s = cosr; cc = -sinr; } else { s = sinr; cc = cosr; }
    if (q & 2) { s = -s; cc = -cc; }

    int row = tensor * 32 + b;
    int off = row * D_LEN + feat;
    g_a[off] = m;
    g_s[off] = s;
    g_c[off] = cc;
}

// ---------------- pair kernel ------------------------------------------------
__device__ __forceinline__ void cp16(uint32_t dst, const float* src) {
    asm volatile("cp.async.cg.shared.global [%0], [%1], 16;\n" :: "r"(dst), "l"(src));
}
__device__ __forceinline__ float wgt(int u, int v, bool diag) {
    if (diag && u >= v) return 0.0f;
    return ((u < 32) == (v < 32)) ? 1.0f : -1.0f;
}

#define TERM1(AU,SU,CU,AV,SV,CV,ACC) do {                      \
    float d_ = (AU) - (AV);                                    \
    float n_ = fmaf((SU), (CV), -((CU) * (SV)));               \
    float q_ = __fdividef(n_, d_);                             \
    (ACC) += (d_ != 0.0f) ? q_ : 100.0f;                       \
} while (0)

#define TERM4(AU,SU,CU,AV,SV,CV,ACC) do {                      \
    TERM1((AU).x,(SU).x,(CU).x,(AV).x,(SV).x,(CV).x,(ACC));    \
    TERM1((AU).y,(SU).y,(CU).y,(AV).y,(SV).y,(CV).y,(ACC));    \
    TERM1((AU).z,(SU).z,(CU).z,(AV).z,(SV).z,(CV).z,(ACC));    \
    TERM1((AU).w,(SU).w,(CU).w,(AV).w,(SV).w,(CV).w,(ACC));    \
} while (0)

// blockDim 256; gridDim (64 k-chunks, 10 tile-pairs)
// smem: 2 buffers x 6 arrays x [16 rows][64 floats] = 49152 bytes exactly
__global__ void __launch_bounds__(256) pair_kernel() {
    __shared__ __align__(16) float smem[12288];
    const int tid = threadIdx.x;
    const int pidx = blockIdx.y;
    const int I = c_PI[pidx], J = c_PJ[pidx];
    const int Ibase = I * 16, Jbase = J * 16;
    const int k0 = blockIdx.x * 512;
    const uint32_t sbase = (uint32_t)__cvta_generic_to_shared(smem);

    const float* srcs[6];
    srcs[0] = g_a + Ibase * D_LEN;
    srcs[1] = g_s + Ibase * D_LEN;
    srcs[2] = g_c + Ibase * D_LEN;
    srcs[3] = g_a + Jbase * D_LEN;
    srcs[4] = g_s + Jbase * D_LEN;
    srcs[5] = g_c + Jbase * D_LEN;

    // loader mapping: one float4 per (array,row,f4-slot) per stage
    const int lrow = tid >> 4;          // 0..15
    const int f4   = tid & 15;          // 0..15
    const int soff = lrow * 64 + ((f4 ^ (lrow & 7)) << 2);   // swizzled float offset
    const int gcol0 = k0 + f4 * 4;

    // prologue: stage 0 -> buffer 0
    #pragma unroll
    for (int arr = 0; arr < 6; ++arr)
        cp16(sbase + 4 * (arr * 1024 + soff), srcs[arr] + lrow * D_LEN + gcol0);
    asm volatile("cp.async.commit_group;\n");

    // compute mapping: 2x2 register tile, 4-way k split
    const int kq = tid >> 6;            // 0..3
    const int tu = (tid >> 3) & 7;      // 0..7
    const int tv = tid & 7;             // 0..7
    float acc00 = 0.f, acc01 = 0.f, acc10 = 0.f, acc11 = 0.f;

    const int ru0 = tu, ru1 = tu + 8, rv0 = tv, rv1 = tv + 8;

    for (int st = 0; st < 8; ++st) {
        const int buf = st & 1;
        if (st + 1 < 8) {
            const int nb = buf ^ 1;
            #pragma unroll
            for (int arr = 0; arr < 6; ++arr)
                cp16(sbase + 4 * (nb * 6144 + arr * 1024 + soff),
                     srcs[arr] + lrow * D_LEN + gcol0 + (st + 1) * 64);
            asm volatile("cp.async.commit_group;\n");
            asm volatile("cp.async.wait_group 1;\n");
        } else {
            asm volatile("cp.async.wait_group 0;\n");
        }
        __syncthreads();

        const float* sb = smem + buf * 6144;
        #pragma unroll
        for (int i = 0; i < 4; ++i) {
            const int f = kq * 4 + i;
            const int ou0 = ru0 * 64 + ((f ^ (ru0 & 7)) << 2);
            const int ou1 = ru1 * 64 + ((f ^ (ru1 & 7)) << 2);
            const int ov0 = rv0 * 64 + ((f ^ (rv0 & 7)) << 2);
            const int ov1 = rv1 * 64 + ((f ^ (rv1 & 7)) << 2);
            float4 au0 = *(const float4*)(sb +        ou0);
            float4 su0 = *(const float4*)(sb + 1024 + ou0);
            float4 cu0 = *(const float4*)(sb + 2048 + ou0);
            float4 au1 = *(const float4*)(sb +        ou1);
            float4 su1 = *(const float4*)(sb + 1024 + ou1);
            float4 cu1 = *(const float4*)(sb + 2048 + ou1);
            float4 av0 = *(const float4*)(sb + 3072 + ov0);
            float4 sv0 = *(const float4*)(sb + 4096 + ov0);
            float4 cv0 = *(const float4*)(sb + 5120 + ov0);
            float4 av1 = *(const float4*)(sb + 3072 + ov1);
            float4 sv1 = *(const float4*)(sb + 4096 + ov1);
            float4 cv1 = *(const float4*)(sb + 5120 + ov1);
            TERM4(au0, su0, cu0, av0, sv0, cv0, acc00);
            TERM4(au0, su0, cu0, av1, sv1, cv1, acc01);
            TERM4(au1, su1, cu1, av0, sv0, cv0, acc10);
            TERM4(au1, su1, cu1, av1, sv1, cv1, acc11);
        }
        __syncthreads();
    }

    // weights (diagonal tile-pairs count only u<v; cross-tensor sign -1)
    const bool diag = (I == J);
    const int u0 = Ibase + tu, u1 = Ibase + tu + 8;
    const int v0 = Jbase + tv, v1 = Jbase + tv + 8;
    float tot = wgt(u0, v0, diag) * acc00 + wgt(u0, v1, diag) * acc01
              + wgt(u1, v0, diag) * acc10 + wgt(u1, v1, diag) * acc11;

    // deterministic block reduction in double
    double td = (double)tot;
    #pragma unroll
    for (int off = 16; off; off >>= 1)
        td += __shfl_down_sync(0xffffffffu, td, off);
    double* red = (double*)smem;   // smem free after trailing sync above
    const int warp = tid >> 5, lane = tid & 31;
    if (lane == 0) red[warp] = td;
    __syncthreads();
    if (tid == 0) {
        double ss = 0.0;
        #pragma unroll
        for (int i = 0; i < 8; ++i) ss += red[i];
        g_part[blockIdx.y * 64 + blockIdx.x] = ss;
    }
}

// ---------------- final deterministic reduction ------------------------------
__global__ void final_kernel(float* __restrict__ out) {
    const int tid = threadIdx.x;
    double s = 0.0;
    for (int i = tid; i < 640; i += 256) s += g_part[i];
    #pragma unroll
    for (int off = 16; off; off >>= 1)
        s += __shfl_down_sync(0xffffffffu, s, off);
    __shared__ double red[8];
    if ((tid & 31) == 0) red[tid >> 5] = s;
    __syncthreads();
    if (tid == 0) {
        double t = 0.0;
        #pragma unroll
        for (int i = 0; i < 8; ++i) t += red[i];
        // result = 6.25 (diagonal, 2*32*T/1024) + 2/(1024*D) * signed pair sum
        out[0] = (float)(6.25 + t * (2.0 / 33554432.0));
    }
}

// ---------------- launch ------------------------------------------------------
extern "C" void kernel_launch(void* const* d_in, const int* in_sizes, int n_in,
                              void* d_out, int out_size) {
    (void)in_sizes; (void)n_in; (void)out_size;
    const float* A = (const float*)d_in[0];
    const float* B = (const float*)d_in[1];
    pool_kernel<<<8192, 256>>>(A, B);
    pair_kernel<<<dim3(64, 10), 256>>>();
    final_kernel<<<1, 256>>>((float*)d_out);
}

// round 3
// speedup vs baseline: 1.0872x; 1.0872x over previous
#include <cuda_runtime.h>
#include <cstdint>

#define D_LEN 32768

// ---------------- scratch (static device globals, no allocation) ------------
__device__ __align__(256) float g_a[64 * D_LEN];
__device__ __align__(256) float g_s[64 * D_LEN];
__device__ __align__(256) float g_c[64 * D_LEN];
__device__ double g_part[1280];

__constant__ int c_PI[10] = {0,0,0,0,1,1,1,2,2,3};
__constant__ int c_PJ[10] = {0,1,2,3,1,2,3,2,3,3};

// ---------------- pool(4) + accurate sincos(100*m) --------------------------
__global__ void pool_kernel(const float* __restrict__ A, const float* __restrict__ B) {
    int idx = blockIdx.x * blockDim.x + threadIdx.x;   // [0, 2*32*32768)
    int tensor = idx >> 20;
    int rem = idx & 1048575;
    int b    = rem >> 15;                              // 0..31
    int feat = rem & 32767;                            // c*256 + ph*16 + pw
    int c  = feat >> 8;
    int ph = (feat >> 4) & 15;
    int pw = feat & 15;
    const float* src = tensor ? B : A;
    const float* p = src + ((((b * 128 + c) * 64) + ph * 4) * 64 + pw * 4);
    float4 r0 = __ldcs((const float4*)(p));
    float4 r1 = __ldcs((const float4*)(p + 64));
    float4 r2 = __ldcs((const float4*)(p + 128));
    float4 r3 = __ldcs((const float4*)(p + 192));
    float sum = ((r0.x + r0.y) + (r0.z + r0.w))
              + ((r1.x + r1.y) + (r1.z + r1.w))
              + ((r2.x + r2.y) + (r2.z + r2.w))
              + ((r3.x + r3.y) + (r3.z + r3.w));
    float m = sum * 0.0625f;

    // sincos(100*m): double range reduction, float polys on [-pi/4, pi/4]
    double xd = 100.0 * (double)m;
    double kd = rint(xd * 0.63661977236758134308);     // 2/pi
    int q = (int)kd;
    float r = (float)(xd - kd * 1.5707963267948966);
    float z = r * r;
    float ps = fmaf(z, fmaf(z, -1.9515295891e-4f, 8.3321608736e-3f), -1.6666654611e-1f);
    float sinr = fmaf(r * z, ps, r);
    float pc = fmaf(z, fmaf(z, 2.443315711809948e-5f, -1.388731625493765e-3f),
                    4.166664568298827e-2f);
    float cosr = fmaf(z * z, pc, fmaf(z, -0.5f, 1.0f));
    float s, cc;
    if (q & 1) { s = cosr; cc = -sinr; } else { s = sinr; cc = cosr; }
    if (q & 2) { s = -s; cc = -cc; }

    int row = tensor * 32 + b;
    int off = row * D_LEN + feat;
    g_a[off] = m;
    g_s[off] = s;
    g_c[off] = cc;
}

// ---------------- pair kernel ------------------------------------------------
__device__ __forceinline__ void cp16(uint32_t dst, const float* src) {
    asm volatile("cp.async.cg.shared.global [%0], [%1], 16;\n" :: "r"(dst), "l"(src));
}
__device__ __forceinline__ float frcp(float x) {
    float r; asm("rcp.approx.ftz.f32 %0, %1;" : "=f"(r) : "f"(x)); return r;
}
__device__ __forceinline__ float wgt(int u, int v, bool diag) {
    if (diag && u >= v) return 0.0f;
    return ((u < 32) == (v < 32)) ? 1.0f : -1.0f;
}

// d = au-av; term = sin(100*d)/d, with d==0 -> 100 (exact-collision guard).
#define TERM1(AU,SU,CU,AV,SV,CV,ACC) do {                      \
    float d_ = (AU) - (AV);                                    \
    float r_ = frcp(d_);                                       \
    float n_ = fmaf((SU), (CV), -((CU) * (SV)));               \
    if (d_ != 0.0f) (ACC) = fmaf(n_, r_, (ACC));               \
    else            (ACC) += 100.0f;                           \
} while (0)

#define TERM4(AU,SU,CU,AV,SV,CV,ACC) do {                      \
    TERM1((AU).x,(SU).x,(CU).x,(AV).x,(SV).x,(CV).x,(ACC));    \
    TERM1((AU).y,(SU).y,(CU).y,(AV).y,(SV).y,(CV).y,(ACC));    \
    TERM1((AU).z,(SU).z,(CU).z,(AV).z,(SV).z,(CV).z,(ACC));    \
    TERM1((AU).w,(SU).w,(CU).w,(AV).w,(SV).w,(CV).w,(ACC));    \
} while (0)

// Padded smem layout, NO swizzle: row stride 36 floats (rows hit distinct
// bank quads since 36 mod 32 = 4). Per buffer: 6 arrays x 16 rows x 36 floats.
// 2 buffers x 3456 floats = 6912 floats = 27648 B.
#define ROWSTR 36
#define ARRSTR 576            /* 16*36 */
#define BUFSTR 3456           /* 6*576 */
#define KSTAGE 32
#define NSTAGE 8              /* 256 k per block */

__global__ void __launch_bounds__(256, 3) pair_kernel() {
    __shared__ __align__(16) float smem[2 * BUFSTR];
    __shared__ double red[8];
    const int tid = threadIdx.x;
    const int pidx = blockIdx.y;
    const int I = c_PI[pidx], J = c_PJ[pidx];
    const int Ibase = I * 16, Jbase = J * 16;
    const int k0 = blockIdx.x * (KSTAGE * NSTAGE);
    const uint32_t sbase = (uint32_t)__cvta_generic_to_shared(smem);

    const float* srcs[6];
    srcs[0] = g_a + Ibase * D_LEN;
    srcs[1] = g_s + Ibase * D_LEN;
    srcs[2] = g_c + Ibase * D_LEN;
    srcs[3] = g_a + Jbase * D_LEN;
    srcs[4] = g_s + Jbase * D_LEN;
    srcs[5] = g_c + Jbase * D_LEN;

    // loader mapping: 768 float4 per stage = 3 per thread
    int larr[3], lgoff[3], lsoff[3];
    #pragma unroll
    for (int j = 0; j < 3; ++j) {
        int item = j * 256 + tid;
        int arr  = item >> 7;
        int rem  = item & 127;
        int row  = rem >> 3;
        int slot = rem & 7;
        larr[j]  = arr;
        lsoff[j] = arr * ARRSTR + row * ROWSTR + slot * 4;   // float offset
        lgoff[j] = row * D_LEN + k0 + slot * 4;              // float offset from srcs[arr]
    }

    // prologue: stage 0 -> buffer 0
    #pragma unroll
    for (int j = 0; j < 3; ++j)
        cp16(sbase + 4 * lsoff[j], srcs[larr[j]] + lgoff[j]);
    asm volatile("cp.async.commit_group;\n");

    // compute mapping: 2x2 register tile, 4-way k split over the 8 f4 slots
    const int kq = tid >> 6;            // 0..3  -> slots {2kq, 2kq+1}
    const int tu = (tid >> 3) & 7;      // 0..7
    const int tv = tid & 7;             // 0..7
    float acc00 = 0.f, acc01 = 0.f, acc10 = 0.f, acc11 = 0.f;

    const int ubase = tu * ROWSTR + kq * 8;                  // in a-array (u tile)
    const int vbase = 3 * ARRSTR + tv * ROWSTR + kq * 8;     // in a-array (v tile)

    for (int st = 0; st < NSTAGE; ++st) {
        const int buf = st & 1;
        if (st + 1 < NSTAGE) {
            const int nb = buf ^ 1;
            #pragma unroll
            for (int j = 0; j < 3; ++j)
                cp16(sbase + 4 * (nb * BUFSTR + lsoff[j]),
                     srcs[larr[j]] + lgoff[j] + (st + 1) * KSTAGE);
            asm volatile("cp.async.commit_group;\n");
            asm volatile("cp.async.wait_group 1;\n");
        } else {
            asm volatile("cp.async.wait_group 0;\n");
        }
        __syncthreads();

        const float* ub = smem + buf * BUFSTR + ubase;
        const float* vb = smem + buf * BUFSTR + vbase;
        #pragma unroll
        for (int i = 0; i < 2; ++i) {
            const int o = i * 4;
            float4 au0 = *(const float4*)(ub + o);
            float4 su0 = *(const float4*)(ub + o + ARRSTR);
            float4 cu0 = *(const float4*)(ub + o + 2 * ARRSTR);
            float4 au1 = *(const float4*)(ub + o + 8 * ROWSTR);
            float4 su1 = *(const float4*)(ub + o + 8 * ROWSTR + ARRSTR);
            float4 cu1 = *(const float4*)(ub + o + 8 * ROWSTR + 2 * ARRSTR);
            float4 av0 = *(const float4*)(vb + o);
            float4 sv0 = *(const float4*)(vb + o + ARRSTR);
            float4 cv0 = *(const float4*)(vb + o + 2 * ARRSTR);
            float4 av1 = *(const float4*)(vb + o + 8 * ROWSTR);
            float4 sv1 = *(const float4*)(vb + o + 8 * ROWSTR + ARRSTR);
            float4 cv1 = *(const float4*)(vb + o + 8 * ROWSTR + 2 * ARRSTR);
            TERM4(au0, su0, cu0, av0, sv0, cv0, acc00);
            TERM4(au0, su0, cu0, av1, sv1, cv1, acc01);
            TERM4(au1, su1, cu1, av0, sv0, cv0, acc10);
            TERM4(au1, su1, cu1, av1, sv1, cv1, acc11);
        }
        __syncthreads();
    }

    // weights (diagonal tile-pairs count only u<v; cross-tensor sign -1)
    const bool diag = (I == J);
    const int u0 = Ibase + tu, u1 = Ibase + tu + 8;
    const int v0 = Jbase + tv, v1 = Jbase + tv + 8;
    float tot = wgt(u0, v0, diag) * acc00 + wgt(u0, v1, diag) * acc01
              + wgt(u1, v0, diag) * acc10 + wgt(u1, v1, diag) * acc11;

    // deterministic block reduction in double
    double td = (double)tot;
    #pragma unroll
    for (int off = 16; off; off >>= 1)
        td += __shfl_down_sync(0xffffffffu, td, off);
    const int warp = tid >> 5, lane = tid & 31;
    if (lane == 0) red[warp] = td;
    __syncthreads();
    if (tid == 0) {
        double ss = 0.0;
        #pragma unroll
        for (int i = 0; i < 8; ++i) ss += red[i];
        g_part[blockIdx.y * 128 + blockIdx.x] = ss;
    }
}

// ---------------- final deterministic reduction ------------------------------
__global__ void final_kernel(float* __restrict__ out) {
    const int tid = threadIdx.x;
    double s = 0.0;
    for (int i = tid; i < 1280; i += 256) s += g_part[i];
    #pragma unroll
    for (int off = 16; off; off >>= 1)
        s += __shfl_down_sync(0xffffffffu, s, off);
    __shared__ double red[8];
    if ((tid & 31) == 0) red[tid >> 5] = s;
    __syncthreads();
    if (tid == 0) {
        double t = 0.0;
        #pragma unroll
        for (int i = 0; i < 8; ++i) t += red[i];
        // result = 6.25 (diagonal, 2*32*T/1024) + 2/(1024*D) * signed pair sum
        out[0] = (float)(6.25 + t * (2.0 / 33554432.0));
    }
}

// ---------------- launch ------------------------------------------------------
extern "C" void kernel_launch(void* const* d_in, const int* in_sizes, int n_in,
                              void* d_out, int out_size) {
    (void)in_sizes; (void)n_in; (void)out_size;
    const float* A = (const float*)d_in[0];
    const float* B = (const float*)d_in[1];
    pool_kernel<<<8192, 256>>>(A, B);
    pair_kernel<<<dim3(128, 10), 256>>>();
    final_kernel<<<1, 256>>>((float*)d_out);
}